// round 7
// baseline (speedup 1.0000x reference)
#include <cuda_runtime.h>

#define ROWS 49
#define NTHREADS 256

__device__ __forceinline__ float rcp_approx(float x) {
    float r;
    asm("rcp.approx.f32 %0, %1;" : "=f"(r) : "f"(x));
    return r;
}

// Cost for one row against 4 register-resident targets (independent per-j chains).
__device__ __forceinline__ float4 row_cost4(
    float4 c0, float4 c1, float pa,
    const float4 t[4], const float twd[4], const float thd[4], const int lb[4],
    const float* __restrict__ pr)
{
    float4 res;
#pragma unroll
    for (int j = 0; j < 4; ++j) {
        float tx = t[j].x, ty = t[j].y, tz = t[j].z, tw = t[j].w;
        float base = pr[lb[j]];                          // 5 - p
        float l1 = fabsf(c0.x - tx) + fabsf(c0.y - ty)
                 + fabsf(c0.z - tz) + fabsf(c0.w - tw);
        float iw = fminf(c1.z, tz) - fmaxf(c1.x, tx);
        float ih = fminf(c1.w, tw) - fmaxf(c1.y, ty);
        float inter = fmaxf(iw, 0.f) * fmaxf(ih, 0.f);
        float ew = (c0.z + twd[j]) - iw;                 // pw + twd - iw
        float eh = (c0.w + thd[j]) - ih;                 // ph + thd - ih
        float ae = ew * eh;
        float uni = fmaf(twd[j], thd[j], pa) - inter;    // pa + a2 - inter
        float num = fmaf(uni, uni, inter * ae);
        float q   = num * rcp_approx(uni * ae);
        float acc = fmaf(5.f, l1, base);
        (&res.x)[j] = fmaf(-2.f, q, acc);
    }
    return res;
}

__global__ __launch_bounds__(NTHREADS, 2)
void matcher_cost_kernel7(const float* __restrict__ logits,   // [BN, C]
                          const float* __restrict__ pboxes,   // [BN, 4] cxcywh
                          const int*   __restrict__ tlabw,    // T labels (int32 or int64 words)
                          const float* __restrict__ tboxes,   // [T, 4] raw (used as-is)
                          float* __restrict__ out,            // [BN, T]
                          int BN, int C, int T)
{
    extern __shared__ float sm[];
    float*  sprob = sm;                                   // ROWS * C  (stores 5 - p)
    int prob_off = (ROWS * C + 3) & ~3;                   // 16B align
    float4* srow  = (float4*)(sm + prob_off);             // ROWS * 3 float4

    const int tid  = threadIdx.x;
    const int row0 = blockIdx.x * ROWS;

    // ---- detect int64 vs int32 label storage (odd 32-bit words all zero) ----
    bool is64 = false;
    if (T >= 8) {
        is64 = (tlabw[1] == 0) & (tlabw[3] == 0) & (tlabw[5] == 0) & (tlabw[7] == 0) &
               (tlabw[9] == 0) & (tlabw[11] == 0) & (tlabw[13] == 0) & (tlabw[15] == 0);
    }

    // ---- per-row prediction-box constants (12 floats each, 3 float4) ----
    if (tid < ROWS) {
        int row = row0 + tid;
        if (row < BN) {
            float4 b = ((const float4*)pboxes)[row];
            float px0 = b.x - 0.5f * b.z, py0 = b.y - 0.5f * b.w;
            float px1 = b.x + 0.5f * b.z, py1 = b.y + 0.5f * b.w;
            srow[tid * 3 + 0] = b;                                  // cx cy pw ph
            srow[tid * 3 + 1] = make_float4(px0, py0, px1, py1);
            srow[tid * 3 + 2] = make_float4((px1 - px0) * (py1 - py0), 0.f, 0.f, 0.f);
        }
    }

    // ---- softmax (one warp per row, strided); store 5 - p ----
    {
        int warp = tid >> 5, lane = tid & 31;
        for (int lr = warp; lr < ROWS; lr += NTHREADS / 32) {
            int row = row0 + lr;
            if (row >= BN) continue;
            const float* lg = logits + (size_t)row * C;
            float m = -3.4e38f;
            for (int c = lane; c < C; c += 32) m = fmaxf(m, __ldg(lg + c));
#pragma unroll
            for (int o = 16; o; o >>= 1) m = fmaxf(m, __shfl_xor_sync(0xFFFFFFFFu, m, o));
            float s = 0.f;
            float* pr = sprob + lr * C;
            for (int c = lane; c < C; c += 32) {
                float e = __expf(__ldg(lg + c) - m);
                s += e;
                pr[c] = e;
            }
#pragma unroll
            for (int o = 16; o; o >>= 1) s += __shfl_xor_sync(0xFFFFFFFFu, s, o);
            float ninv = -1.0f / s;
            for (int c = lane; c < C; c += 32) pr[c] = fmaf(pr[c], ninv, 5.0f);
        }
    }
    __syncthreads();

    const int rows_here = min(ROWS, BN - row0);
    const int tb0 = 4 * tid;
    if (tb0 >= T) return;                    // after the barrier; safe

    // ---- load this thread's 4 targets into registers ----
    const float4* tb4 = (const float4*)tboxes;
    const bool full = (tb0 + 4 <= T);
    const int nv = min(4, T - tb0);

    float4 t[4];
    float  twd[4], thd[4];
    int    lb[4];
#pragma unroll
    for (int j = 0; j < 4; ++j) {
        if (j < nv) {
            t[j]  = tb4[tb0 + j];
            lb[j] = is64 ? tlabw[2 * (tb0 + j)] : tlabw[tb0 + j];
        } else {
            t[j]  = make_float4(0.f, 0.f, 1.f, 1.f);
            lb[j] = 0;
        }
        twd[j] = t[j].z - t[j].x;   // target "width"  (xyxy interp)
        thd[j] = t[j].w - t[j].y;   // target "height"
    }

    float* optr = out + (size_t)row0 * T + tb0;

    if (full) {
        // ---- branch-free hot loop: 2 independent rows per iteration ----
        int r = 0;
        for (; r + 1 < rows_here; r += 2, optr += 2 * T) {
            float4 c0a = srow[r * 3 + 0];
            float4 c1a = srow[r * 3 + 1];
            float  paa = srow[r * 3 + 2].x;
            float4 c0b = srow[r * 3 + 3];
            float4 c1b = srow[r * 3 + 4];
            float  pab = srow[r * 3 + 5].x;

            float4 ra = row_cost4(c0a, c1a, paa, t, twd, thd, lb, sprob + r * C);
            float4 rb = row_cost4(c0b, c1b, pab, t, twd, thd, lb, sprob + (r + 1) * C);

            *(float4*)optr = ra;
            *(float4*)(optr + T) = rb;
        }
        if (r < rows_here) {
            float4 res = row_cost4(srow[r * 3 + 0], srow[r * 3 + 1], srow[r * 3 + 2].x,
                                   t, twd, thd, lb, sprob + r * C);
            *(float4*)optr = res;
        }
    } else {
        // ---- rare tail chunk: scalar stores ----
        for (int r = 0; r < rows_here; ++r, optr += T) {
            float4 res = row_cost4(srow[r * 3 + 0], srow[r * 3 + 1], srow[r * 3 + 2].x,
                                   t, twd, thd, lb, sprob + r * C);
#pragma unroll
            for (int j = 0; j < 4; ++j)
                if (j < nv) optr[j] = (&res.x)[j];
        }
    }
}

extern "C" void kernel_launch(void* const* d_in, const int* in_sizes, int n_in,
                              void* d_out, int out_size)
{
    const float* logits = (const float*)d_in[0];   // out_labels [B,N,C]
    const float* pboxes = (const float*)d_in[1];   // out_bboxes [B,N,4]
    const int*   tlabw  = (const int*)d_in[2];     // tgt_labels [T] (int32 or int64)
    const float* tboxes = (const float*)d_in[3];   // tgt_bboxes [T,4]
    float* out = (float*)d_out;

    int BN = in_sizes[1] / 4;
    int C  = in_sizes[0] / BN;
    int T  = in_sizes[2];

    int prob_off = (ROWS * C + 3) & ~3;
    size_t smem = (size_t)(prob_off + ROWS * 12) * sizeof(float) + 16;

    int grid = (BN + ROWS - 1) / ROWS;
    matcher_cost_kernel7<<<grid, NTHREADS, smem>>>(logits, pboxes, tlabw, tboxes,
                                                   out, BN, C, T);
}

// round 8
// speedup vs baseline: 1.1088x; 1.1088x over previous
#include <cuda_runtime.h>

#define NTHREADS 256
#define ROWS 36
#define STR  37   // transposed prob stride (odd -> conflict-free)

__device__ __forceinline__ float rcp_approx(float x) {
    float r;
    asm("rcp.approx.f32 %0, %1;" : "=f"(r) : "f"(x));
    return r;
}

__device__ __forceinline__ bool detect_is64(const int* __restrict__ tlabw) {
    return (tlabw[1] == 0) & (tlabw[3] == 0) & (tlabw[5] == 0) & (tlabw[7] == 0) &
           (tlabw[9] == 0) & (tlabw[11] == 0) & (tlabw[13] == 0) & (tlabw[15] == 0);
}

// ===================== fast path: compile-time T, C; BN % ROWS == 0 ==========
template<int TT, int CC>
__global__ __launch_bounds__(NTHREADS, 3)
void matcher_fast(const float* __restrict__ logits,   // [BN, CC]
                  const float* __restrict__ pboxes,   // [BN, 4]
                  const int*   __restrict__ tlabw,    // TT labels (int32/int64 words)
                  const float* __restrict__ tboxes,   // [TT, 4]
                  float* __restrict__ out)            // [BN, TT]
{
    __shared__ float  sprobT[CC * STR];   // [c][r], stores 5 - p
    __shared__ float4 srow[ROWS * 2];     // per row: (cx cy pw ph), (px0 py0 px1 py1)

    const int tid  = threadIdx.x;
    const int row0 = blockIdx.x * ROWS;

    const bool is64 = detect_is64(tlabw);

    if (tid < ROWS) {
        float4 b = ((const float4*)pboxes)[row0 + tid];
        float px0 = b.x - 0.5f * b.z, py0 = b.y - 0.5f * b.w;
        float px1 = b.x + 0.5f * b.z, py1 = b.y + 0.5f * b.w;
        srow[tid * 2 + 0] = b;
        srow[tid * 2 + 1] = make_float4(px0, py0, px1, py1);
    }

    // ---- softmax into transposed table: sprobT[c*STR + r] = 5 - p ----
    {
        int warp = tid >> 5, lane = tid & 31;
        for (int lr = warp; lr < ROWS; lr += NTHREADS / 32) {
            const float* lg = logits + (size_t)(row0 + lr) * CC;
            float m = -3.4e38f;
#pragma unroll
            for (int c = lane; c < CC; c += 32) m = fmaxf(m, __ldg(lg + c));
#pragma unroll
            for (int o = 16; o; o >>= 1) m = fmaxf(m, __shfl_xor_sync(0xFFFFFFFFu, m, o));
            float s = 0.f;
#pragma unroll
            for (int c = lane; c < CC; c += 32) {
                float e = __expf(__ldg(lg + c) - m);
                s += e;
                sprobT[c * STR + lr] = e;
            }
#pragma unroll
            for (int o = 16; o; o >>= 1) s += __shfl_xor_sync(0xFFFFFFFFu, s, o);
            float ninv = -1.0f / s;
#pragma unroll
            for (int c = lane; c < CC; c += 32)
                sprobT[c * STR + lr] = fmaf(sprobT[c * STR + lr], ninv, 5.0f);
        }
    }
    __syncthreads();

    const int tb0 = 4 * tid;
    if (tb0 >= TT) return;

    // ---- 4 register-resident targets + fixed prob-row pointers ----
    const float4* tb4 = (const float4*)tboxes;
    float4 t[4];
    float  twd[4], thd[4], ta2[4];
    const float* qp[4];
#pragma unroll
    for (int j = 0; j < 4; ++j) {
        t[j] = tb4[tb0 + j];
        int lb = is64 ? tlabw[2 * (tb0 + j)] : tlabw[tb0 + j];
        qp[j] = sprobT + lb * STR;
        twd[j] = t[j].z - t[j].x;
        thd[j] = t[j].w - t[j].y;
        ta2[j] = twd[j] * thd[j];
    }

    float* optr = out + (size_t)row0 * TT + tb0;
    const float4* sr = srow;

#pragma unroll 1
    for (int k = 0; k < ROWS / 6; ++k) {
#pragma unroll
        for (int g = 0; g < 6; ++g) {
            float4 c0 = sr[g * 2 + 0];          // broadcast LDS, imm offset
            float4 c1 = sr[g * 2 + 1];
            float  pa = c0.z * c0.w;
            float4 res;
#pragma unroll
            for (int j = 0; j < 4; ++j) {
                float base = qp[j][g];          // LDS, imm offset, no addr math
                float l1 = fabsf(c0.x - t[j].x) + fabsf(c0.y - t[j].y)
                         + fabsf(c0.z - t[j].z) + fabsf(c0.w - t[j].w);
                float iw = fminf(c1.z, t[j].z) - fmaxf(c1.x, t[j].x);
                float ih = fminf(c1.w, t[j].w) - fmaxf(c1.y, t[j].y);
                float inter = fmaxf(iw, 0.f) * fmaxf(ih, 0.f);
                float ew = (c0.z + twd[j]) - iw;        // min+max identity
                float eh = (c0.w + thd[j]) - ih;
                float ae = ew * eh;
                float uni = (pa + ta2[j]) - inter;
                float num = fmaf(uni, uni, inter * ae);
                float q   = num * rcp_approx(uni * ae);
                (&res.x)[j] = fmaf(-2.f, q, fmaf(5.f, l1, base));
            }
            *(float4*)(optr + g * TT) = res;    // imm offset (TT compile-time)
        }
        sr += 12;
        optr += 6 * TT;
#pragma unroll
        for (int j = 0; j < 4; ++j) qp[j] += 6;
    }
}

// ===================== generic fallback (R6 structure) ========================
#define GROWS 33

__device__ __forceinline__ float4 g_row_cost4(
    float4 c0, float4 c1, float pa,
    const float4 t[4], const float twd[4], const float thd[4], const int lb[4],
    const float* __restrict__ pr)
{
    float4 res;
#pragma unroll
    for (int j = 0; j < 4; ++j) {
        float base = pr[lb[j]];
        float l1 = fabsf(c0.x - t[j].x) + fabsf(c0.y - t[j].y)
                 + fabsf(c0.z - t[j].z) + fabsf(c0.w - t[j].w);
        float iw = fminf(c1.z, t[j].z) - fmaxf(c1.x, t[j].x);
        float ih = fminf(c1.w, t[j].w) - fmaxf(c1.y, t[j].y);
        float inter = fmaxf(iw, 0.f) * fmaxf(ih, 0.f);
        float ew = (c0.z + twd[j]) - iw;
        float eh = (c0.w + thd[j]) - ih;
        float ae = ew * eh;
        float uni = fmaf(twd[j], thd[j], pa) - inter;
        float num = fmaf(uni, uni, inter * ae);
        float q   = num * rcp_approx(uni * ae);
        (&res.x)[j] = fmaf(-2.f, q, fmaf(5.f, l1, base));
    }
    return res;
}

__global__ __launch_bounds__(NTHREADS, 3)
void matcher_generic(const float* __restrict__ logits,
                     const float* __restrict__ pboxes,
                     const int*   __restrict__ tlabw,
                     const float* __restrict__ tboxes,
                     float* __restrict__ out,
                     int BN, int C, int T)
{
    extern __shared__ float sm[];
    float*  sprob = sm;
    int prob_off = (GROWS * C + 3) & ~3;
    float4* srow = (float4*)(sm + prob_off);

    const int tid  = threadIdx.x;
    const int row0 = blockIdx.x * GROWS;

    bool is64 = false;
    if (T >= 8) is64 = detect_is64(tlabw);

    if (tid < GROWS) {
        int row = row0 + tid;
        if (row < BN) {
            float4 b = ((const float4*)pboxes)[row];
            float px0 = b.x - 0.5f * b.z, py0 = b.y - 0.5f * b.w;
            float px1 = b.x + 0.5f * b.z, py1 = b.y + 0.5f * b.w;
            srow[tid * 3 + 0] = b;
            srow[tid * 3 + 1] = make_float4(px0, py0, px1, py1);
            srow[tid * 3 + 2] = make_float4((px1 - px0) * (py1 - py0), 0.f, 0.f, 0.f);
        }
    }
    {
        int warp = tid >> 5, lane = tid & 31;
        for (int lr = warp; lr < GROWS; lr += NTHREADS / 32) {
            int row = row0 + lr;
            if (row >= BN) continue;
            const float* lg = logits + (size_t)row * C;
            float m = -3.4e38f;
            for (int c = lane; c < C; c += 32) m = fmaxf(m, __ldg(lg + c));
#pragma unroll
            for (int o = 16; o; o >>= 1) m = fmaxf(m, __shfl_xor_sync(0xFFFFFFFFu, m, o));
            float s = 0.f;
            float* pr = sprob + lr * C;
            for (int c = lane; c < C; c += 32) {
                float e = __expf(__ldg(lg + c) - m);
                s += e;
                pr[c] = e;
            }
#pragma unroll
            for (int o = 16; o; o >>= 1) s += __shfl_xor_sync(0xFFFFFFFFu, s, o);
            float ninv = -1.0f / s;
            for (int c = lane; c < C; c += 32) pr[c] = fmaf(pr[c], ninv, 5.0f);
        }
    }
    __syncthreads();

    const int rows_here = min(GROWS, BN - row0);
    const float4* tb4 = (const float4*)tboxes;

    for (int tb0 = 4 * tid; tb0 < T; tb0 += 4 * NTHREADS) {
        int nv = min(4, T - tb0);
        bool full = (nv == 4);
        float4 t[4]; float twd[4], thd[4]; int lb[4];
#pragma unroll
        for (int j = 0; j < 4; ++j) {
            if (j < nv) {
                t[j]  = tb4[tb0 + j];
                lb[j] = is64 ? tlabw[2 * (tb0 + j)] : tlabw[tb0 + j];
            } else { t[j] = make_float4(0.f, 0.f, 1.f, 1.f); lb[j] = 0; }
            twd[j] = t[j].z - t[j].x;
            thd[j] = t[j].w - t[j].y;
        }
        float* optr = out + (size_t)row0 * T + tb0;
        for (int r = 0; r < rows_here; ++r, optr += T) {
            float4 res = g_row_cost4(srow[r * 3], srow[r * 3 + 1], srow[r * 3 + 2].x,
                                     t, twd, thd, lb, sprob + r * C);
            if (full) *(float4*)optr = res;
            else {
#pragma unroll
                for (int j = 0; j < 4; ++j) if (j < nv) optr[j] = (&res.x)[j];
            }
        }
    }
}

// ===================== dispatch ================================================
extern "C" void kernel_launch(void* const* d_in, const int* in_sizes, int n_in,
                              void* d_out, int out_size)
{
    const float* logits = (const float*)d_in[0];
    const float* pboxes = (const float*)d_in[1];
    const int*   tlabw  = (const int*)d_in[2];
    const float* tboxes = (const float*)d_in[3];
    float* out = (float*)d_out;

    int BN = in_sizes[1] / 4;
    int C  = in_sizes[0] / BN;
    int T  = in_sizes[2];

    if (T == 960 && C == 92 && (BN % ROWS) == 0) {
        matcher_fast<960, 92><<<BN / ROWS, NTHREADS>>>(logits, pboxes, tlabw, tboxes, out);
    } else {
        int prob_off = (GROWS * C + 3) & ~3;
        size_t smem = (size_t)(prob_off + GROWS * 12) * sizeof(float) + 16;
        int grid = (BN + GROWS - 1) / GROWS;
        matcher_generic<<<grid, NTHREADS, smem>>>(logits, pboxes, tlabw, tboxes,
                                                  out, BN, C, T);
    }
}

// round 9
// speedup vs baseline: 1.1439x; 1.0316x over previous
#include <cuda_runtime.h>

#define NTHREADS 256
#define ROWSF 33   // fast-path rows per block -> grid 437 (<=444, balanced 3/SM)
#define STR   33   // transposed prob stride (odd -> conflict-free)

__device__ __forceinline__ float rcp_approx(float x) {
    float r;
    asm("rcp.approx.f32 %0, %1;" : "=f"(r) : "f"(x));
    return r;
}

__device__ __forceinline__ bool detect_is64(const int* __restrict__ tlabw) {
    return (tlabw[1] == 0) & (tlabw[3] == 0) & (tlabw[5] == 0) & (tlabw[7] == 0) &
           (tlabw[9] == 0) & (tlabw[11] == 0) & (tlabw[13] == 0) & (tlabw[15] == 0);
}

// ===================== fast path: compile-time T, C ===========================
template<int TT, int CC>
__global__ __launch_bounds__(NTHREADS, 3)
void matcher_fast(const float* __restrict__ logits,   // [BN, CC]
                  const float* __restrict__ pboxes,   // [BN, 4]
                  const int*   __restrict__ tlabw,    // TT labels (int32/int64 words)
                  const float* __restrict__ tboxes,   // [TT, 4]
                  float* __restrict__ out,            // [BN, TT]
                  int BN)
{
    __shared__ float  sprobT[CC * STR];    // [c][r], stores 5 - p
    __shared__ float4 srow[ROWSF * 2];     // per row: (cx cy pw ph), (px0 py0 px1 py1)

    const int tid  = threadIdx.x;
    const int row0 = blockIdx.x * ROWSF;
    const int rows_here = min(ROWSF, BN - row0);

    const bool is64 = detect_is64(tlabw);

    if (tid < ROWSF && tid < rows_here) {
        float4 b = ((const float4*)pboxes)[row0 + tid];
        float px0 = b.x - 0.5f * b.z, py0 = b.y - 0.5f * b.w;
        float px1 = b.x + 0.5f * b.z, py1 = b.y + 0.5f * b.w;
        srow[tid * 2 + 0] = b;
        srow[tid * 2 + 1] = make_float4(px0, py0, px1, py1);
    }

    // ---- softmax into transposed table: sprobT[c*STR + r] = 5 - p ----
    {
        int warp = tid >> 5, lane = tid & 31;
        for (int lr = warp; lr < rows_here; lr += NTHREADS / 32) {
            const float* lg = logits + (size_t)(row0 + lr) * CC;
            float m = -3.4e38f;
#pragma unroll
            for (int c = lane; c < CC; c += 32) m = fmaxf(m, __ldg(lg + c));
#pragma unroll
            for (int o = 16; o; o >>= 1) m = fmaxf(m, __shfl_xor_sync(0xFFFFFFFFu, m, o));
            float s = 0.f;
#pragma unroll
            for (int c = lane; c < CC; c += 32) {
                float e = __expf(__ldg(lg + c) - m);
                s += e;
                sprobT[c * STR + lr] = e;
            }
#pragma unroll
            for (int o = 16; o; o >>= 1) s += __shfl_xor_sync(0xFFFFFFFFu, s, o);
            float ninv = -1.0f / s;
#pragma unroll
            for (int c = lane; c < CC; c += 32)
                sprobT[c * STR + lr] = fmaf(sprobT[c * STR + lr], ninv, 5.0f);
        }
    }
    __syncthreads();

    const int tb0 = 4 * tid;
    if (tb0 >= TT) return;

    // ---- 4 register-resident targets + fixed prob-row pointers ----
    const float4* tb4 = (const float4*)tboxes;
    float4 t[4];
    float  twd[4], thd[4], ta2[4];
    const float* qp[4];
#pragma unroll
    for (int j = 0; j < 4; ++j) {
        t[j] = tb4[tb0 + j];
        int lb = is64 ? tlabw[2 * (tb0 + j)] : tlabw[tb0 + j];
        qp[j] = sprobT + lb * STR;
        twd[j] = t[j].z - t[j].x;
        thd[j] = t[j].w - t[j].y;
        ta2[j] = twd[j] * thd[j];
    }

    float* optr = out + (size_t)row0 * TT + tb0;
    const float4* sr = srow;

    const int ngroups = rows_here / 3;   // 33 and 12 both divide by 3
#pragma unroll 1
    for (int k = 0; k < ngroups; ++k) {
#pragma unroll
        for (int g = 0; g < 3; ++g) {
            float4 c0 = sr[g * 2 + 0];          // broadcast LDS, imm offset
            float4 c1 = sr[g * 2 + 1];
            float  pa = c0.z * c0.w;
            float4 res;
#pragma unroll
            for (int j = 0; j < 4; ++j) {
                float base = qp[j][g];          // LDS, imm offset
                float l1 = fabsf(c0.x - t[j].x) + fabsf(c0.y - t[j].y)
                         + fabsf(c0.z - t[j].z) + fabsf(c0.w - t[j].w);
                float iw = fminf(c1.z, t[j].z) - fmaxf(c1.x, t[j].x);
                float ih = fminf(c1.w, t[j].w) - fmaxf(c1.y, t[j].y);
                float inter = fmaxf(iw, 0.f) * fmaxf(ih, 0.f);
                float ew = (c0.z + twd[j]) - iw;        // min+max identity
                float eh = (c0.w + thd[j]) - ih;
                float ae = ew * eh;
                float uni = (pa + ta2[j]) - inter;
                float num = fmaf(uni, uni, inter * ae);
                float q   = num * rcp_approx(uni * ae);
                (&res.x)[j] = fmaf(-2.f, q, fmaf(5.f, l1, base));
            }
            *(float4*)(optr + g * TT) = res;    // imm offset (TT compile-time)
        }
        sr += 6;
        optr += 3 * TT;
#pragma unroll
        for (int j = 0; j < 4; ++j) qp[j] += 3;
    }
    // generic tail (rows_here % 3 != 0 never happens for BN=14400, kept for safety)
    for (int r = 3 * ngroups; r < rows_here; ++r, optr += TT) {
        float4 c0 = sr[0]; float4 c1 = sr[1]; sr += 2;
        float pa = c0.z * c0.w;
        float4 res;
#pragma unroll
        for (int j = 0; j < 4; ++j) {
            float base = qp[j][0];
            float l1 = fabsf(c0.x - t[j].x) + fabsf(c0.y - t[j].y)
                     + fabsf(c0.z - t[j].z) + fabsf(c0.w - t[j].w);
            float iw = fminf(c1.z, t[j].z) - fmaxf(c1.x, t[j].x);
            float ih = fminf(c1.w, t[j].w) - fmaxf(c1.y, t[j].y);
            float inter = fmaxf(iw, 0.f) * fmaxf(ih, 0.f);
            float ew = (c0.z + twd[j]) - iw;
            float eh = (c0.w + thd[j]) - ih;
            float ae = ew * eh;
            float uni = (pa + ta2[j]) - inter;
            float num = fmaf(uni, uni, inter * ae);
            float q   = num * rcp_approx(uni * ae);
            (&res.x)[j] = fmaf(-2.f, q, fmaf(5.f, l1, base));
        }
        *(float4*)optr = res;
#pragma unroll
        for (int j = 0; j < 4; ++j) qp[j] += 1;
    }
}

// ===================== generic fallback ========================================
#define GROWS 33

__device__ __forceinline__ float4 g_row_cost4(
    float4 c0, float4 c1, float pa,
    const float4 t[4], const float twd[4], const float thd[4], const int lb[4],
    const float* __restrict__ pr)
{
    float4 res;
#pragma unroll
    for (int j = 0; j < 4; ++j) {
        float base = pr[lb[j]];
        float l1 = fabsf(c0.x - t[j].x) + fabsf(c0.y - t[j].y)
                 + fabsf(c0.z - t[j].z) + fabsf(c0.w - t[j].w);
        float iw = fminf(c1.z, t[j].z) - fmaxf(c1.x, t[j].x);
        float ih = fminf(c1.w, t[j].w) - fmaxf(c1.y, t[j].y);
        float inter = fmaxf(iw, 0.f) * fmaxf(ih, 0.f);
        float ew = (c0.z + twd[j]) - iw;
        float eh = (c0.w + thd[j]) - ih;
        float ae = ew * eh;
        float uni = fmaf(twd[j], thd[j], pa) - inter;
        float num = fmaf(uni, uni, inter * ae);
        float q   = num * rcp_approx(uni * ae);
        (&res.x)[j] = fmaf(-2.f, q, fmaf(5.f, l1, base));
    }
    return res;
}

__global__ __launch_bounds__(NTHREADS, 3)
void matcher_generic(const float* __restrict__ logits,
                     const float* __restrict__ pboxes,
                     const int*   __restrict__ tlabw,
                     const float* __restrict__ tboxes,
                     float* __restrict__ out,
                     int BN, int C, int T)
{
    extern __shared__ float sm[];
    float*  sprob = sm;
    int prob_off = (GROWS * C + 3) & ~3;
    float4* srow = (float4*)(sm + prob_off);

    const int tid  = threadIdx.x;
    const int row0 = blockIdx.x * GROWS;

    bool is64 = false;
    if (T >= 8) is64 = detect_is64(tlabw);

    if (tid < GROWS) {
        int row = row0 + tid;
        if (row < BN) {
            float4 b = ((const float4*)pboxes)[row];
            float px0 = b.x - 0.5f * b.z, py0 = b.y - 0.5f * b.w;
            float px1 = b.x + 0.5f * b.z, py1 = b.y + 0.5f * b.w;
            srow[tid * 3 + 0] = b;
            srow[tid * 3 + 1] = make_float4(px0, py0, px1, py1);
            srow[tid * 3 + 2] = make_float4((px1 - px0) * (py1 - py0), 0.f, 0.f, 0.f);
        }
    }
    {
        int warp = tid >> 5, lane = tid & 31;
        for (int lr = warp; lr < GROWS; lr += NTHREADS / 32) {
            int row = row0 + lr;
            if (row >= BN) continue;
            const float* lg = logits + (size_t)row * C;
            float m = -3.4e38f;
            for (int c = lane; c < C; c += 32) m = fmaxf(m, __ldg(lg + c));
#pragma unroll
            for (int o = 16; o; o >>= 1) m = fmaxf(m, __shfl_xor_sync(0xFFFFFFFFu, m, o));
            float s = 0.f;
            float* pr = sprob + lr * C;
            for (int c = lane; c < C; c += 32) {
                float e = __expf(__ldg(lg + c) - m);
                s += e;
                pr[c] = e;
            }
#pragma unroll
            for (int o = 16; o; o >>= 1) s += __shfl_xor_sync(0xFFFFFFFFu, s, o);
            float ninv = -1.0f / s;
            for (int c = lane; c < C; c += 32) pr[c] = fmaf(pr[c], ninv, 5.0f);
        }
    }
    __syncthreads();

    const int rows_here = min(GROWS, BN - row0);
    const float4* tb4 = (const float4*)tboxes;

    for (int tb0 = 4 * tid; tb0 < T; tb0 += 4 * NTHREADS) {
        int nv = min(4, T - tb0);
        bool full = (nv == 4);
        float4 t[4]; float twd[4], thd[4]; int lb[4];
#pragma unroll
        for (int j = 0; j < 4; ++j) {
            if (j < nv) {
                t[j]  = tb4[tb0 + j];
                lb[j] = is64 ? tlabw[2 * (tb0 + j)] : tlabw[tb0 + j];
            } else { t[j] = make_float4(0.f, 0.f, 1.f, 1.f); lb[j] = 0; }
            twd[j] = t[j].z - t[j].x;
            thd[j] = t[j].w - t[j].y;
        }
        float* optr = out + (size_t)row0 * T + tb0;
        for (int r = 0; r < rows_here; ++r, optr += T) {
            float4 res = g_row_cost4(srow[r * 3], srow[r * 3 + 1], srow[r * 3 + 2].x,
                                     t, twd, thd, lb, sprob + r * C);
            if (full) *(float4*)optr = res;
            else {
#pragma unroll
                for (int j = 0; j < 4; ++j) if (j < nv) optr[j] = (&res.x)[j];
            }
        }
    }
}

// ===================== dispatch ================================================
extern "C" void kernel_launch(void* const* d_in, const int* in_sizes, int n_in,
                              void* d_out, int out_size)
{
    const float* logits = (const float*)d_in[0];
    const float* pboxes = (const float*)d_in[1];
    const int*   tlabw  = (const int*)d_in[2];
    const float* tboxes = (const float*)d_in[3];
    float* out = (float*)d_out;

    int BN = in_sizes[1] / 4;
    int C  = in_sizes[0] / BN;
    int T  = in_sizes[2];

    if (T == 960 && C == 92 && BN >= 8) {
        int grid = (BN + ROWSF - 1) / ROWSF;   // 437 for BN=14400: 98.4% wave balance
        matcher_fast<960, 92><<<grid, NTHREADS>>>(logits, pboxes, tlabw, tboxes, out, BN);
    } else {
        int prob_off = (GROWS * C + 3) & ~3;
        size_t smem = (size_t)(prob_off + GROWS * 12) * sizeof(float) + 16;
        int grid = (BN + GROWS - 1) / GROWS;
        matcher_generic<<<grid, NTHREADS, smem>>>(logits, pboxes, tlabw, tboxes,
                                                  out, BN, C, T);
    }
}

// round 10
// speedup vs baseline: 1.2364x; 1.0809x over previous
#include <cuda_runtime.h>

#define NTHREADS 256
#define ROWSF 33   // grid 437 (<=444): single balanced wave at 3 CTA/SM
#define STR   33   // transposed prob stride (odd -> conflict-free)

__device__ __forceinline__ float rcp_approx(float x) {
    float r;
    asm("rcp.approx.f32 %0, %1;" : "=f"(r) : "f"(x));
    return r;
}

// ---- packed f32x2 helpers (Blackwell). IEEE rn => bitwise same as scalar. ----
__device__ __forceinline__ float2 f2add(float2 a, float2 b) {
    float2 r;
    asm("{\n\t.reg .b64 ra,rb,rc;\n\t"
        "mov.b64 ra,{%2,%3};\n\tmov.b64 rb,{%4,%5};\n\t"
        "add.rn.f32x2 rc,ra,rb;\n\t"
        "mov.b64 {%0,%1},rc;\n\t}"
        : "=f"(r.x), "=f"(r.y) : "f"(a.x), "f"(a.y), "f"(b.x), "f"(b.y));
    return r;
}
__device__ __forceinline__ float2 f2sub(float2 a, float2 b) {
    float2 r;
    asm("{\n\t.reg .b64 ra,rb,rc;\n\t"
        "mov.b64 ra,{%2,%3};\n\tmov.b64 rb,{%4,%5};\n\t"
        "sub.rn.f32x2 rc,ra,rb;\n\t"
        "mov.b64 {%0,%1},rc;\n\t}"
        : "=f"(r.x), "=f"(r.y) : "f"(a.x), "f"(a.y), "f"(b.x), "f"(b.y));
    return r;
}
__device__ __forceinline__ float2 f2mul(float2 a, float2 b) {
    float2 r;
    asm("{\n\t.reg .b64 ra,rb,rc;\n\t"
        "mov.b64 ra,{%2,%3};\n\tmov.b64 rb,{%4,%5};\n\t"
        "mul.rn.f32x2 rc,ra,rb;\n\t"
        "mov.b64 {%0,%1},rc;\n\t}"
        : "=f"(r.x), "=f"(r.y) : "f"(a.x), "f"(a.y), "f"(b.x), "f"(b.y));
    return r;
}
__device__ __forceinline__ float2 f2fma(float2 a, float2 b, float2 c) {
    float2 r;
    asm("{\n\t.reg .b64 ra,rb,rc,rd;\n\t"
        "mov.b64 ra,{%2,%3};\n\tmov.b64 rb,{%4,%5};\n\tmov.b64 rc,{%6,%7};\n\t"
        "fma.rn.f32x2 rd,ra,rb,rc;\n\t"
        "mov.b64 {%0,%1},rd;\n\t}"
        : "=f"(r.x), "=f"(r.y)
        : "f"(a.x), "f"(a.y), "f"(b.x), "f"(b.y), "f"(c.x), "f"(c.y));
    return r;
}

__device__ __forceinline__ bool detect_is64(const int* __restrict__ tlabw) {
    return (tlabw[1] == 0) & (tlabw[3] == 0) & (tlabw[5] == 0) & (tlabw[7] == 0) &
           (tlabw[9] == 0) & (tlabw[11] == 0) & (tlabw[13] == 0) & (tlabw[15] == 0);
}

// ===================== fast path: compile-time T, C ===========================
template<int TT, int CC>
__global__ __launch_bounds__(NTHREADS, 3)
void matcher_fast(const float* __restrict__ logits,
                  const float* __restrict__ pboxes,
                  const int*   __restrict__ tlabw,
                  const float* __restrict__ tboxes,
                  float* __restrict__ out,
                  int BN)
{
    __shared__ float  sprobT[CC * STR];    // [c][r], stores 5 - p
    __shared__ float4 srow[ROWSF * 2];

    const int tid  = threadIdx.x;
    const int row0 = blockIdx.x * ROWSF;
    const int rows_here = min(ROWSF, BN - row0);

    const bool is64 = detect_is64(tlabw);

    if (tid < rows_here) {
        float4 b = ((const float4*)pboxes)[row0 + tid];
        float px0 = b.x - 0.5f * b.z, py0 = b.y - 0.5f * b.w;
        float px1 = b.x + 0.5f * b.z, py1 = b.y + 0.5f * b.w;
        srow[tid * 2 + 0] = b;
        srow[tid * 2 + 1] = make_float4(px0, py0, px1, py1);
    }

    // ---- softmax into transposed table ----
    {
        int warp = tid >> 5, lane = tid & 31;
        for (int lr = warp; lr < rows_here; lr += NTHREADS / 32) {
            const float* lg = logits + (size_t)(row0 + lr) * CC;
            float m = -3.4e38f;
#pragma unroll
            for (int c = lane; c < CC; c += 32) m = fmaxf(m, __ldg(lg + c));
#pragma unroll
            for (int o = 16; o; o >>= 1) m = fmaxf(m, __shfl_xor_sync(0xFFFFFFFFu, m, o));
            float s = 0.f;
#pragma unroll
            for (int c = lane; c < CC; c += 32) {
                float e = __expf(__ldg(lg + c) - m);
                s += e;
                sprobT[c * STR + lr] = e;
            }
#pragma unroll
            for (int o = 16; o; o >>= 1) s += __shfl_xor_sync(0xFFFFFFFFu, s, o);
            float ninv = -1.0f / s;
#pragma unroll
            for (int c = lane; c < CC; c += 32)
                sprobT[c * STR + lr] = fmaf(sprobT[c * STR + lr], ninv, 5.0f);
        }
    }
    __syncthreads();

    const int tb0 = 4 * tid;
    if (tb0 >= TT) return;

    // ---- 4 register-resident targets ----
    const float4* tb4 = (const float4*)tboxes;
    float4 t[4];
    float2 twh[4];       // (twd, thd)
    float2 ta2p[2];      // (ta2_0, ta2_1), (ta2_2, ta2_3)
    const float* qp[4];
#pragma unroll
    for (int j = 0; j < 4; ++j) {
        t[j] = tb4[tb0 + j];
        int lb = is64 ? tlabw[2 * (tb0 + j)] : tlabw[tb0 + j];
        qp[j] = sprobT + lb * STR;
        twh[j] = make_float2(t[j].z - t[j].x, t[j].w - t[j].y);
    }
    ta2p[0] = make_float2(twh[0].x * twh[0].y, twh[1].x * twh[1].y);
    ta2p[1] = make_float2(twh[2].x * twh[2].y, twh[3].x * twh[3].y);

    float* optr = out + (size_t)row0 * TT + tb0;
    const float4* sr = srow;

    const int ngroups = rows_here / 3;
#pragma unroll 1
    for (int k = 0; k < ngroups; ++k) {
#pragma unroll
        for (int g = 0; g < 3; ++g) {
            float4 c0 = sr[g * 2 + 0];
            float4 c1 = sr[g * 2 + 1];
            float2 c0xy = make_float2(c0.x, c0.y);
            float2 c0zw = make_float2(c0.z, c0.w);
            float  pa = c0.z * c0.w;
            float2 pa2 = make_float2(pa, pa);
            float2 unib01 = f2add(pa2, ta2p[0]);   // pa + ta2, packed per pair
            float2 unib23 = f2add(pa2, ta2p[1]);

            float inter[4], ae[4], acc[4];
#pragma unroll
            for (int j = 0; j < 4; ++j) {
                float base = qp[j][g];
                float2 dxy = f2sub(c0xy, make_float2(t[j].x, t[j].y));
                float2 dzw = f2sub(c0zw, make_float2(t[j].z, t[j].w));
                float l1 = fabsf(dxy.x) + fabsf(dxy.y) + fabsf(dzw.x) + fabsf(dzw.y);
                float iw = fminf(c1.z, t[j].z) - fmaxf(c1.x, t[j].x);
                float ih = fminf(c1.w, t[j].w) - fmaxf(c1.y, t[j].y);
                inter[j] = fmaxf(iw, 0.f) * fmaxf(ih, 0.f);
                float2 ewh = f2sub(f2add(c0zw, twh[j]), make_float2(iw, ih));
                ae[j] = ewh.x * ewh.y;
                acc[j] = fmaf(5.f, l1, base);
            }

            // ---- packed post-intersection chain, 2 targets per lane-pair ----
            float2 in01 = make_float2(inter[0], inter[1]);
            float2 in23 = make_float2(inter[2], inter[3]);
            float2 ae01 = make_float2(ae[0], ae[1]);
            float2 ae23 = make_float2(ae[2], ae[3]);

            float2 uni01 = f2sub(unib01, in01);
            float2 uni23 = f2sub(unib23, in23);
            float2 ie01  = f2mul(in01, ae01);
            float2 ie23  = f2mul(in23, ae23);
            float2 num01 = f2fma(uni01, uni01, ie01);
            float2 num23 = f2fma(uni23, uni23, ie23);
            float2 den01 = f2mul(uni01, ae01);
            float2 den23 = f2mul(uni23, ae23);
            float2 r01 = make_float2(rcp_approx(den01.x), rcp_approx(den01.y));
            float2 r23 = make_float2(rcp_approx(den23.x), rcp_approx(den23.y));
            float2 q01 = f2mul(num01, r01);
            float2 q23 = f2mul(num23, r23);

            float4 res;
            res.x = fmaf(-2.f, q01.x, acc[0]);
            res.y = fmaf(-2.f, q01.y, acc[1]);
            res.z = fmaf(-2.f, q23.x, acc[2]);
            res.w = fmaf(-2.f, q23.y, acc[3]);
            *(float4*)(optr + g * TT) = res;
        }
        sr += 6;
        optr += 3 * TT;
#pragma unroll
        for (int j = 0; j < 4; ++j) qp[j] += 3;
    }
}

// ===================== generic fallback ========================================
#define GROWS 33

__global__ __launch_bounds__(NTHREADS, 3)
void matcher_generic(const float* __restrict__ logits,
                     const float* __restrict__ pboxes,
                     const int*   __restrict__ tlabw,
                     const float* __restrict__ tboxes,
                     float* __restrict__ out,
                     int BN, int C, int T)
{
    extern __shared__ float sm[];
    float*  sprob = sm;
    int prob_off = (GROWS * C + 3) & ~3;
    float4* srow = (float4*)(sm + prob_off);

    const int tid  = threadIdx.x;
    const int row0 = blockIdx.x * GROWS;

    bool is64 = false;
    if (T >= 8) is64 = detect_is64(tlabw);

    if (tid < GROWS) {
        int row = row0 + tid;
        if (row < BN) {
            float4 b = ((const float4*)pboxes)[row];
            float px0 = b.x - 0.5f * b.z, py0 = b.y - 0.5f * b.w;
            float px1 = b.x + 0.5f * b.z, py1 = b.y + 0.5f * b.w;
            srow[tid * 3 + 0] = b;
            srow[tid * 3 + 1] = make_float4(px0, py0, px1, py1);
            srow[tid * 3 + 2] = make_float4((px1 - px0) * (py1 - py0), 0.f, 0.f, 0.f);
        }
    }
    {
        int warp = tid >> 5, lane = tid & 31;
        for (int lr = warp; lr < GROWS; lr += NTHREADS / 32) {
            int row = row0 + lr;
            if (row >= BN) continue;
            const float* lg = logits + (size_t)row * C;
            float m = -3.4e38f;
            for (int c = lane; c < C; c += 32) m = fmaxf(m, __ldg(lg + c));
#pragma unroll
            for (int o = 16; o; o >>= 1) m = fmaxf(m, __shfl_xor_sync(0xFFFFFFFFu, m, o));
            float s = 0.f;
            float* pr = sprob + lr * C;
            for (int c = lane; c < C; c += 32) {
                float e = __expf(__ldg(lg + c) - m);
                s += e;
                pr[c] = e;
            }
#pragma unroll
            for (int o = 16; o; o >>= 1) s += __shfl_xor_sync(0xFFFFFFFFu, s, o);
            float ninv = -1.0f / s;
            for (int c = lane; c < C; c += 32) pr[c] = fmaf(pr[c], ninv, 5.0f);
        }
    }
    __syncthreads();

    const int rows_here = min(GROWS, BN - row0);
    const float4* tb4 = (const float4*)tboxes;

    for (int tb0 = 4 * tid; tb0 < T; tb0 += 4 * NTHREADS) {
        int nv = min(4, T - tb0);
        bool full = (nv == 4);
        float4 t[4]; float twd[4], thd[4]; int lb[4];
#pragma unroll
        for (int j = 0; j < 4; ++j) {
            if (j < nv) {
                t[j]  = tb4[tb0 + j];
                lb[j] = is64 ? tlabw[2 * (tb0 + j)] : tlabw[tb0 + j];
            } else { t[j] = make_float4(0.f, 0.f, 1.f, 1.f); lb[j] = 0; }
            twd[j] = t[j].z - t[j].x;
            thd[j] = t[j].w - t[j].y;
        }
        float* optr = out + (size_t)row0 * T + tb0;
        for (int r = 0; r < rows_here; ++r, optr += T) {
            float4 c0 = srow[r * 3], c1 = srow[r * 3 + 1];
            float pa = srow[r * 3 + 2].x;
            const float* pr = sprob + r * C;
            float4 res;
#pragma unroll
            for (int j = 0; j < 4; ++j) {
                float base = pr[lb[j]];
                float l1 = fabsf(c0.x - t[j].x) + fabsf(c0.y - t[j].y)
                         + fabsf(c0.z - t[j].z) + fabsf(c0.w - t[j].w);
                float iw = fminf(c1.z, t[j].z) - fmaxf(c1.x, t[j].x);
                float ih = fminf(c1.w, t[j].w) - fmaxf(c1.y, t[j].y);
                float inter = fmaxf(iw, 0.f) * fmaxf(ih, 0.f);
                float ew = (c0.z + twd[j]) - iw;
                float eh = (c0.w + thd[j]) - ih;
                float ae = ew * eh;
                float uni = fmaf(twd[j], thd[j], pa) - inter;
                float num = fmaf(uni, uni, inter * ae);
                float q   = num * rcp_approx(uni * ae);
                (&res.x)[j] = fmaf(-2.f, q, fmaf(5.f, l1, base));
            }
            if (full) *(float4*)optr = res;
            else {
#pragma unroll
                for (int j = 0; j < 4; ++j) if (j < nv) optr[j] = (&res.x)[j];
            }
        }
    }
}

// ===================== dispatch ================================================
extern "C" void kernel_launch(void* const* d_in, const int* in_sizes, int n_in,
                              void* d_out, int out_size)
{
    const float* logits = (const float*)d_in[0];
    const float* pboxes = (const float*)d_in[1];
    const int*   tlabw  = (const int*)d_in[2];
    const float* tboxes = (const float*)d_in[3];
    float* out = (float*)d_out;

    int BN = in_sizes[1] / 4;
    int C  = in_sizes[0] / BN;
    int T  = in_sizes[2];

    if (T == 960 && C == 92 && BN >= 8 && (BN % 3) == 0) {
        int grid = (BN + ROWSF - 1) / ROWSF;
        matcher_fast<960, 92><<<grid, NTHREADS>>>(logits, pboxes, tlabw, tboxes, out, BN);
    } else {
        int prob_off = (GROWS * C + 3) & ~3;
        size_t smem = (size_t)(prob_off + GROWS * 12) * sizeof(float) + 16;
        int grid = (BN + GROWS - 1) / GROWS;
        matcher_generic<<<grid, NTHREADS, smem>>>(logits, pboxes, tlabw, tboxes,
                                                  out, BN, C, T);
    }
}

// round 11
// speedup vs baseline: 1.2490x; 1.0102x over previous
#include <cuda_runtime.h>

#define NTHREADS 256
#define ROWSF 33   // grid 437 (<=444): single balanced wave at 3 CTA/SM
#define STR   33   // transposed prob stride (odd -> conflict-free)

__device__ __forceinline__ float rcp_approx(float x) {
    float r;
    asm("rcp.approx.f32 %0, %1;" : "=f"(r) : "f"(x));
    return r;
}

// ---- packed f32x2 helpers (Blackwell). IEEE rn => bitwise same as scalar. ----
__device__ __forceinline__ float2 f2add(float2 a, float2 b) {
    float2 r;
    asm("{\n\t.reg .b64 ra,rb,rc;\n\t"
        "mov.b64 ra,{%2,%3};\n\tmov.b64 rb,{%4,%5};\n\t"
        "add.rn.f32x2 rc,ra,rb;\n\t"
        "mov.b64 {%0,%1},rc;\n\t}"
        : "=f"(r.x), "=f"(r.y) : "f"(a.x), "f"(a.y), "f"(b.x), "f"(b.y));
    return r;
}
__device__ __forceinline__ float2 f2sub(float2 a, float2 b) {
    float2 r;
    asm("{\n\t.reg .b64 ra,rb,rc;\n\t"
        "mov.b64 ra,{%2,%3};\n\tmov.b64 rb,{%4,%5};\n\t"
        "sub.rn.f32x2 rc,ra,rb;\n\t"
        "mov.b64 {%0,%1},rc;\n\t}"
        : "=f"(r.x), "=f"(r.y) : "f"(a.x), "f"(a.y), "f"(b.x), "f"(b.y));
    return r;
}
__device__ __forceinline__ float2 f2mul(float2 a, float2 b) {
    float2 r;
    asm("{\n\t.reg .b64 ra,rb,rc;\n\t"
        "mov.b64 ra,{%2,%3};\n\tmov.b64 rb,{%4,%5};\n\t"
        "mul.rn.f32x2 rc,ra,rb;\n\t"
        "mov.b64 {%0,%1},rc;\n\t}"
        : "=f"(r.x), "=f"(r.y) : "f"(a.x), "f"(a.y), "f"(b.x), "f"(b.y));
    return r;
}
__device__ __forceinline__ float2 f2fma(float2 a, float2 b, float2 c) {
    float2 r;
    asm("{\n\t.reg .b64 ra,rb,rc,rd;\n\t"
        "mov.b64 ra,{%2,%3};\n\tmov.b64 rb,{%4,%5};\n\tmov.b64 rc,{%6,%7};\n\t"
        "fma.rn.f32x2 rd,ra,rb,rc;\n\t"
        "mov.b64 {%0,%1},rd;\n\t}"
        : "=f"(r.x), "=f"(r.y)
        : "f"(a.x), "f"(a.y), "f"(b.x), "f"(b.y), "f"(c.x), "f"(c.y));
    return r;
}

__device__ __forceinline__ bool detect_is64(const int* __restrict__ tlabw) {
    return (tlabw[1] == 0) & (tlabw[3] == 0) & (tlabw[5] == 0) & (tlabw[7] == 0) &
           (tlabw[9] == 0) & (tlabw[11] == 0) & (tlabw[13] == 0) & (tlabw[15] == 0);
}

// ===================== fast path: compile-time T, C ===========================
template<int TT, int CC>
__global__ __launch_bounds__(NTHREADS, 3)
void matcher_fast(const float* __restrict__ logits,
                  const float* __restrict__ pboxes,
                  const int*   __restrict__ tlabw,
                  const float* __restrict__ tboxes,
                  float* __restrict__ out,
                  int BN)
{
    __shared__ float  sprobT[CC * STR];    // [c][r], stores 5 - p
    __shared__ float4 srow[ROWSF * 2];

    const int tid  = threadIdx.x;
    const int row0 = blockIdx.x * ROWSF;
    const int rows_here = min(ROWSF, BN - row0);

    const bool is64 = detect_is64(tlabw);

    if (tid < rows_here) {
        float4 b = ((const float4*)pboxes)[row0 + tid];
        float px0 = b.x - 0.5f * b.z, py0 = b.y - 0.5f * b.w;
        float px1 = b.x + 0.5f * b.z, py1 = b.y + 0.5f * b.w;
        srow[tid * 2 + 0] = b;
        srow[tid * 2 + 1] = make_float4(px0, py0, px1, py1);
    }

    // ---- softmax into transposed table ----
    {
        int warp = tid >> 5, lane = tid & 31;
        for (int lr = warp; lr < rows_here; lr += NTHREADS / 32) {
            const float* lg = logits + (size_t)(row0 + lr) * CC;
            float m = -3.4e38f;
#pragma unroll
            for (int c = lane; c < CC; c += 32) m = fmaxf(m, __ldg(lg + c));
#pragma unroll
            for (int o = 16; o; o >>= 1) m = fmaxf(m, __shfl_xor_sync(0xFFFFFFFFu, m, o));
            float s = 0.f;
#pragma unroll
            for (int c = lane; c < CC; c += 32) {
                float e = __expf(__ldg(lg + c) - m);
                s += e;
                sprobT[c * STR + lr] = e;
            }
#pragma unroll
            for (int o = 16; o; o >>= 1) s += __shfl_xor_sync(0xFFFFFFFFu, s, o);
            float ninv = -1.0f / s;
#pragma unroll
            for (int c = lane; c < CC; c += 32)
                sprobT[c * STR + lr] = fmaf(sprobT[c * STR + lr], ninv, 5.0f);
        }
    }
    __syncthreads();

    const int tb0 = 4 * tid;
    if (tb0 >= TT) return;

    // ---- 4 register-resident targets ----
    const float4* tb4 = (const float4*)tboxes;
    float4 t[4];
    float2 twh[4];       // (twd, thd)
    float2 ta2p[2];      // (ta2_0, ta2_1), (ta2_2, ta2_3)
    const float* qp[4];
#pragma unroll
    for (int j = 0; j < 4; ++j) {
        t[j] = tb4[tb0 + j];
        int lb = is64 ? tlabw[2 * (tb0 + j)] : tlabw[tb0 + j];
        qp[j] = sprobT + lb * STR;
        twh[j] = make_float2(t[j].z - t[j].x, t[j].w - t[j].y);
    }
    ta2p[0] = make_float2(twh[0].x * twh[0].y, twh[1].x * twh[1].y);
    ta2p[1] = make_float2(twh[2].x * twh[2].y, twh[3].x * twh[3].y);

    float* optr = out + (size_t)row0 * TT + tb0;
    const float4* sr = srow;

    const float2 m2 = make_float2(-2.f, -2.f);

    // one row's 4 costs; all chain values stay packed until the STG
    auto do_row = [&](float4 c0, float4 c1, const float* base_g, int g) -> float4 {
        float2 c0xy = make_float2(c0.x, c0.y);
        float2 c0zw = make_float2(c0.z, c0.w);
        float  pa = c0.z * c0.w;
        float2 pa2 = make_float2(pa, pa);
        float2 unib01 = f2add(pa2, ta2p[0]);
        float2 unib23 = f2add(pa2, ta2p[1]);

        float inter[4], ae[4], acc[4];
#pragma unroll
        for (int j = 0; j < 4; ++j) {
            float base = qp[j][g];
            float2 dxy = f2sub(c0xy, make_float2(t[j].x, t[j].y));
            float2 dzw = f2sub(c0zw, make_float2(t[j].z, t[j].w));
            float l1 = fabsf(dxy.x) + fabsf(dxy.y) + fabsf(dzw.x) + fabsf(dzw.y);
            float iw = fminf(c1.z, t[j].z) - fmaxf(c1.x, t[j].x);
            float ih = fminf(c1.w, t[j].w) - fmaxf(c1.y, t[j].y);
            inter[j] = fmaxf(iw, 0.f) * fmaxf(ih, 0.f);
            float2 ewh = f2sub(f2add(c0zw, twh[j]), make_float2(iw, ih));
            ae[j] = ewh.x * ewh.y;
            acc[j] = fmaf(5.f, l1, base);
        }

        float2 in01 = make_float2(inter[0], inter[1]);
        float2 in23 = make_float2(inter[2], inter[3]);
        float2 ae01 = make_float2(ae[0], ae[1]);
        float2 ae23 = make_float2(ae[2], ae[3]);

        float2 uni01 = f2sub(unib01, in01);
        float2 uni23 = f2sub(unib23, in23);
        float2 ie01  = f2mul(in01, ae01);
        float2 ie23  = f2mul(in23, ae23);
        float2 num01 = f2fma(uni01, uni01, ie01);
        float2 num23 = f2fma(uni23, uni23, ie23);
        float2 den01 = f2mul(uni01, ae01);
        float2 den23 = f2mul(uni23, ae23);
        float2 r01 = make_float2(rcp_approx(den01.x), rcp_approx(den01.y));
        float2 r23 = make_float2(rcp_approx(den23.x), rcp_approx(den23.y));
        float2 q01 = f2mul(num01, r01);
        float2 q23 = f2mul(num23, r23);

        // packed final: q never leaves the pair domain
        float2 res01 = f2fma(m2, q01, make_float2(acc[0], acc[1]));
        float2 res23 = f2fma(m2, q23, make_float2(acc[2], acc[3]));
        return make_float4(res01.x, res01.y, res23.x, res23.y);
    };

    const int ng6 = rows_here / 6;           // 33 -> 5 (+3 tail); 12 -> 2 (+0)
    const int tail = rows_here - 6 * ng6;

#pragma unroll 1
    for (int k = 0; k < ng6; ++k) {
#pragma unroll
        for (int g = 0; g < 6; ++g) {
            float4 res = do_row(sr[g * 2 + 0], sr[g * 2 + 1], nullptr, g);
            *(float4*)(optr + g * TT) = res;
        }
        sr += 12;
        optr += 6 * TT;
#pragma unroll
        for (int j = 0; j < 4; ++j) qp[j] += 6;
    }
#pragma unroll
    for (int g = 0; g < 5; ++g) {            // tail <= 5 rows (3 for ROWSF=33)
        if (g < tail) {
            float4 res = do_row(sr[g * 2 + 0], sr[g * 2 + 1], nullptr, g);
            *(float4*)(optr + g * TT) = res;
        }
    }
}

// ===================== generic fallback ========================================
#define GROWS 33

__global__ __launch_bounds__(NTHREADS, 3)
void matcher_generic(const float* __restrict__ logits,
                     const float* __restrict__ pboxes,
                     const int*   __restrict__ tlabw,
                     const float* __restrict__ tboxes,
                     float* __restrict__ out,
                     int BN, int C, int T)
{
    extern __shared__ float sm[];
    float*  sprob = sm;
    int prob_off = (GROWS * C + 3) & ~3;
    float4* srow = (float4*)(sm + prob_off);

    const int tid  = threadIdx.x;
    const int row0 = blockIdx.x * GROWS;

    bool is64 = false;
    if (T >= 8) is64 = detect_is64(tlabw);

    if (tid < GROWS) {
        int row = row0 + tid;
        if (row < BN) {
            float4 b = ((const float4*)pboxes)[row];
            float px0 = b.x - 0.5f * b.z, py0 = b.y - 0.5f * b.w;
            float px1 = b.x + 0.5f * b.z, py1 = b.y + 0.5f * b.w;
            srow[tid * 3 + 0] = b;
            srow[tid * 3 + 1] = make_float4(px0, py0, px1, py1);
            srow[tid * 3 + 2] = make_float4((px1 - px0) * (py1 - py0), 0.f, 0.f, 0.f);
        }
    }
    {
        int warp = tid >> 5, lane = tid & 31;
        for (int lr = warp; lr < GROWS; lr += NTHREADS / 32) {
            int row = row0 + lr;
            if (row >= BN) continue;
            const float* lg = logits + (size_t)row * C;
            float m = -3.4e38f;
            for (int c = lane; c < C; c += 32) m = fmaxf(m, __ldg(lg + c));
#pragma unroll
            for (int o = 16; o; o >>= 1) m = fmaxf(m, __shfl_xor_sync(0xFFFFFFFFu, m, o));
            float s = 0.f;
            float* pr = sprob + lr * C;
            for (int c = lane; c < C; c += 32) {
                float e = __expf(__ldg(lg + c) - m);
                s += e;
                pr[c] = e;
            }
#pragma unroll
            for (int o = 16; o; o >>= 1) s += __shfl_xor_sync(0xFFFFFFFFu, s, o);
            float ninv = -1.0f / s;
            for (int c = lane; c < C; c += 32) pr[c] = fmaf(pr[c], ninv, 5.0f);
        }
    }
    __syncthreads();

    const int rows_here = min(GROWS, BN - row0);
    const float4* tb4 = (const float4*)tboxes;

    for (int tb0 = 4 * tid; tb0 < T; tb0 += 4 * NTHREADS) {
        int nv = min(4, T - tb0);
        bool full = (nv == 4);
        float4 t[4]; float twd[4], thd[4]; int lb[4];
#pragma unroll
        for (int j = 0; j < 4; ++j) {
            if (j < nv) {
                t[j]  = tb4[tb0 + j];
                lb[j] = is64 ? tlabw[2 * (tb0 + j)] : tlabw[tb0 + j];
            } else { t[j] = make_float4(0.f, 0.f, 1.f, 1.f); lb[j] = 0; }
            twd[j] = t[j].z - t[j].x;
            thd[j] = t[j].w - t[j].y;
        }
        float* optr = out + (size_t)row0 * T + tb0;
        for (int r = 0; r < rows_here; ++r, optr += T) {
            float4 c0 = srow[r * 3], c1 = srow[r * 3 + 1];
            float pa = srow[r * 3 + 2].x;
            const float* pr = sprob + r * C;
            float4 res;
#pragma unroll
            for (int j = 0; j < 4; ++j) {
                float base = pr[lb[j]];
                float l1 = fabsf(c0.x - t[j].x) + fabsf(c0.y - t[j].y)
                         + fabsf(c0.z - t[j].z) + fabsf(c0.w - t[j].w);
                float iw = fminf(c1.z, t[j].z) - fmaxf(c1.x, t[j].x);
                float ih = fminf(c1.w, t[j].w) - fmaxf(c1.y, t[j].y);
                float inter = fmaxf(iw, 0.f) * fmaxf(ih, 0.f);
                float ew = (c0.z + twd[j]) - iw;
                float eh = (c0.w + thd[j]) - ih;
                float ae = ew * eh;
                float uni = fmaf(twd[j], thd[j], pa) - inter;
                float num = fmaf(uni, uni, inter * ae);
                float q   = num * rcp_approx(uni * ae);
                (&res.x)[j] = fmaf(-2.f, q, fmaf(5.f, l1, base));
            }
            if (full) *(float4*)optr = res;
            else {
#pragma unroll
                for (int j = 0; j < 4; ++j) if (j < nv) optr[j] = (&res.x)[j];
            }
        }
    }
}

// ===================== dispatch ================================================
extern "C" void kernel_launch(void* const* d_in, const int* in_sizes, int n_in,
                              void* d_out, int out_size)
{
    const float* logits = (const float*)d_in[0];
    const float* pboxes = (const float*)d_in[1];
    const int*   tlabw  = (const int*)d_in[2];
    const float* tboxes = (const float*)d_in[3];
    float* out = (float*)d_out;

    int BN = in_sizes[1] / 4;
    int C  = in_sizes[0] / BN;
    int T  = in_sizes[2];

    if (T == 960 && C == 92 && BN >= 8) {
        int grid = (BN + ROWSF - 1) / ROWSF;
        matcher_fast<960, 92><<<grid, NTHREADS>>>(logits, pboxes, tlabw, tboxes, out, BN);
    } else {
        int prob_off = (GROWS * C + 3) & ~3;
        size_t smem = (size_t)(prob_off + GROWS * 12) * sizeof(float) + 16;
        int grid = (BN + GROWS - 1) / GROWS;
        matcher_generic<<<grid, NTHREADS, smem>>>(logits, pboxes, tlabw, tboxes,
                                                  out, BN, C, T);
    }
}